// round 1
// baseline (speedup 1.0000x reference)
#include <cuda_runtime.h>

// ---------------------------------------------------------------------------
// Scratch (device-global; no allocations allowed in kernel_launch)
// ---------------------------------------------------------------------------
// q,k,v,attn_out: (B=16, Cd=32, S=64, HW=1024) = 33,554,432 floats each
static __device__ float g_q [33554432];
static __device__ float g_k [33554432];
static __device__ float g_v [33554432];
static __device__ float g_ao[33554432];

// ---------------------------------------------------------------------------
// Packed fp32x2 helpers (FFMA2 is PTX-only; ptxas will not auto-fuse)
// ---------------------------------------------------------------------------
__device__ __forceinline__ unsigned long long pk2(float lo, float hi) {
    unsigned long long r;
    asm("mov.b64 %0, {%1, %2};" : "=l"(r) : "f"(lo), "f"(hi));
    return r;
}
__device__ __forceinline__ void fma2(unsigned long long& d,
                                     unsigned long long a,
                                     unsigned long long b) {
    asm("fma.rn.f32x2 %0, %1, %2, %0;" : "+l"(d) : "l"(a), "l"(b));
}
__device__ __forceinline__ float2 up2(unsigned long long v) {
    float2 f;
    asm("mov.b64 {%0, %1}, %2;" : "=f"(f.x), "=f"(f.y) : "l"(v));
    return f;
}

// ---------------------------------------------------------------------------
// Kernel 1: fused q/k/v conv (1x3x3, pad (1,1) in H/W), per-frame.
// Grid: (strip=8, s=64, b=16). Block: 256 threads.
// Block computes M=96 out channels x 128 pixels (4 rows x 32 cols).
// Thread tile: 6 out-ch x 4 pixel-pairs (f32x2 packed along W).
// ---------------------------------------------------------------------------
__global__ __launch_bounds__(256) void qkv_conv_kernel(
    const float* __restrict__ x,
    const float* __restrict__ wq, const float* __restrict__ bq,
    const float* __restrict__ wk, const float* __restrict__ bk,
    const float* __restrict__ wv, const float* __restrict__ bv)
{
    __shared__ float Xs[64 * 6 * 32];   // 64 in-ch x 6 halo rows x 32 cols = 48KB

    const int strip = blockIdx.x;       // 0..7  -> rows h0..h0+3
    const int s     = blockIdx.y;       // 0..63
    const int b     = blockIdx.z;       // 0..15
    const int tid   = threadIdx.x;
    const int tm    = tid >> 4;         // 0..15 : out-channel group
    const int tn    = tid & 15;         // 0..15 : column-pair
    const int h0    = strip * 4;

    // ---- load halo strip (rows h0-1 .. h0+4, zero outside frame) ----
    const float* xb = x + ((size_t)(b * 64) * 64 + s) * 1024;  // + ic*65536
    for (int idx = tid; idx < 64 * 6 * 32; idx += 256) {
        int ic  = idx / 192;
        int rem = idx - ic * 192;
        int r   = rem >> 5;
        int c   = rem & 31;
        int gh  = h0 - 1 + r;
        float v = 0.f;
        if (gh >= 0 && gh < 32) v = xb[ic * 65536 + gh * 32 + c];
        Xs[idx] = v;
    }
    __syncthreads();

    // ---- per-thread weight rows + bias ----
    const float* wp[6];
    float bias[6];
#pragma unroll
    for (int i = 0; i < 6; i++) {
        int m = tm * 6 + i;              // 0..95
        if (m < 32)      { wp[i] = wq + m * 576;        bias[i] = bq[m]; }
        else if (m < 64) { wp[i] = wk + (m - 32) * 576; bias[i] = bk[m - 32]; }
        else             { wp[i] = wv + (m - 64) * 576; bias[i] = bv[m - 64]; }
    }

    unsigned long long acc[6][4];
#pragma unroll
    for (int i = 0; i < 6; i++)
#pragma unroll
        for (int r = 0; r < 4; r++) acc[i][r] = pk2(bias[i], bias[i]);

    const int c0 = tn * 2;

    for (int ic = 0; ic < 64; ic++) {
        const float* xr = &Xs[ic * 192];
        // pre-pack the 3 horizontal shifts for all 6 halo rows
        unsigned long long pL[6], pC[6], pR[6];
#pragma unroll
        for (int r = 0; r < 6; r++) {
            float x0 = xr[r * 32 + c0];
            float x1 = xr[r * 32 + c0 + 1];
            float xm = (c0 > 0)  ? xr[r * 32 + c0 - 1] : 0.f;
            float x2 = (c0 < 30) ? xr[r * 32 + c0 + 2] : 0.f;
            pL[r] = pk2(xm, x0);
            pC[r] = pk2(x0, x1);
            pR[r] = pk2(x1, x2);
        }
#pragma unroll
        for (int dh = 0; dh < 3; dh++) {
#pragma unroll
            for (int dw = 0; dw < 3; dw++) {
#pragma unroll
                for (int i = 0; i < 6; i++) {
                    float w = wp[i][ic * 9 + dh * 3 + dw];
                    unsigned long long wpk = pk2(w, w);
#pragma unroll
                    for (int r = 0; r < 4; r++) {
                        unsigned long long xv = (dw == 0) ? pL[r + dh]
                                              : (dw == 1) ? pC[r + dh]
                                                          : pR[r + dh];
                        fma2(acc[i][r], xv, wpk);
                    }
                }
            }
        }
    }

    // ---- store ----
#pragma unroll
    for (int i = 0; i < 6; i++) {
        int m  = tm * 6 + i;
        float* dst = (m < 32) ? g_q : (m < 64) ? g_k : g_v;
        int ch = m & 31;
        float* p = dst + ((size_t)(b * 32 + ch) * 64 + s) * 1024 + h0 * 32 + c0;
#pragma unroll
        for (int r = 0; r < 4; r++) {
            *(float2*)(p + r * 32) = up2(acc[i][r]);
        }
    }
}

// ---------------------------------------------------------------------------
// Kernel 2: per-(b,c) attention. 512 blocks x 256 threads.
// Phase A: A[64][64] = sigmoid(q k^T / 32).  Phase B: out = A v.
// ---------------------------------------------------------------------------
__global__ __launch_bounds__(256) void attn_kernel()
{
    __shared__ float A[64 * 64];        // 16KB scores
    __shared__ float Buf[4224];         // Qs[64*33]+Ks[64*33] or Vs[64*65]

    const int bc  = blockIdx.x;         // b*32 + c
    const float* q = g_q + (size_t)bc * 65536;
    const float* k = g_k + (size_t)bc * 65536;
    const float* v = g_v + (size_t)bc * 65536;
    float*       o = g_ao + (size_t)bc * 65536;

    const int tid = threadIdx.x;
    const int ty  = tid >> 4;           // 0..15
    const int tx  = tid & 15;           // 0..15

    float* Qs = Buf;
    float* Ks = Buf + 2112;

    float sc[4][4];
#pragma unroll
    for (int a = 0; a < 4; a++)
#pragma unroll
        for (int c = 0; c < 4; c++) sc[a][c] = 0.f;

    // -------- phase A: scores --------
    for (int f0 = 0; f0 < 1024; f0 += 32) {
#pragma unroll
        for (int i = 0; i < 8; i++) {
            int idx = tid + i * 256;    // 0..2047
            int row = idx >> 5, col = idx & 31;
            Qs[row * 33 + col] = q[row * 1024 + f0 + col];
            Ks[row * 33 + col] = k[row * 1024 + f0 + col];
        }
        __syncthreads();
#pragma unroll
        for (int ff = 0; ff < 32; ff++) {
            float qv[4], kv[4];
#pragma unroll
            for (int u = 0; u < 4; u++) qv[u] = Qs[(ty + 16 * u) * 33 + ff];
#pragma unroll
            for (int u = 0; u < 4; u++) kv[u] = Ks[(tx + 16 * u) * 33 + ff];
#pragma unroll
            for (int us = 0; us < 4; us++)
#pragma unroll
                for (int ut = 0; ut < 4; ut++)
                    sc[us][ut] = fmaf(qv[us], kv[ut], sc[us][ut]);
        }
        __syncthreads();
    }
    const float scale = 0.03125f;       // (H*W)^-0.5 = 1/32
#pragma unroll
    for (int us = 0; us < 4; us++)
#pragma unroll
        for (int ut = 0; ut < 4; ut++) {
            float z = sc[us][ut] * scale;
            A[(ty + 16 * us) * 64 + (tx + 16 * ut)] = 1.f / (1.f + __expf(-z));
        }
    __syncthreads();

    // -------- phase B: out = A * v --------
    float* Vs = Buf;                    // [64][65]
    for (int f0 = 0; f0 < 1024; f0 += 64) {
#pragma unroll
        for (int i = 0; i < 16; i++) {
            int idx = tid + i * 256;    // 0..4095
            int row = idx >> 6, col = idx & 63;
            Vs[row * 65 + col] = v[row * 1024 + f0 + col];
        }
        __syncthreads();
        float oacc[4][4];
#pragma unroll
        for (int a = 0; a < 4; a++)
#pragma unroll
            for (int c = 0; c < 4; c++) oacc[a][c] = 0.f;
        for (int t = 0; t < 64; t++) {
            float av[4], vv[4];
#pragma unroll
            for (int u = 0; u < 4; u++) av[u] = A[(ty + 16 * u) * 64 + t];
#pragma unroll
            for (int u = 0; u < 4; u++) vv[u] = Vs[t * 65 + tx + 16 * u];
#pragma unroll
            for (int us = 0; us < 4; us++)
#pragma unroll
                for (int uf = 0; uf < 4; uf++)
                    oacc[us][uf] = fmaf(av[us], vv[uf], oacc[us][uf]);
        }
#pragma unroll
        for (int us = 0; us < 4; us++)
#pragma unroll
            for (int uf = 0; uf < 4; uf++)
                o[(ty + 16 * us) * 1024 + f0 + tx + 16 * uf] = oacc[us][uf];
        __syncthreads();
    }
}

// ---------------------------------------------------------------------------
// Kernel 3: output conv (Cd=32 -> C=64), 1x3x3, pad (1,1).
// Same structure as kernel 1, M=64, Cin=32. Thread tile 4 x 4 pairs.
// ---------------------------------------------------------------------------
__global__ __launch_bounds__(256) void oconv_kernel(
    const float* __restrict__ wo, const float* __restrict__ bo,
    float* __restrict__ out)
{
    __shared__ float Xs[32 * 6 * 32];   // 24KB

    const int strip = blockIdx.x;
    const int s     = blockIdx.y;
    const int b     = blockIdx.z;
    const int tid   = threadIdx.x;
    const int tm    = tid >> 4;
    const int tn    = tid & 15;
    const int h0    = strip * 4;

    const float* xb = g_ao + ((size_t)(b * 32) * 64 + s) * 1024;
    for (int idx = tid; idx < 32 * 6 * 32; idx += 256) {
        int ic  = idx / 192;
        int rem = idx - ic * 192;
        int r   = rem >> 5;
        int c   = rem & 31;
        int gh  = h0 - 1 + r;
        float v = 0.f;
        if (gh >= 0 && gh < 32) v = xb[ic * 65536 + gh * 32 + c];
        Xs[idx] = v;
    }
    __syncthreads();

    const float* wp[4];
    float bias[4];
#pragma unroll
    for (int i = 0; i < 4; i++) {
        int m = tm * 4 + i;             // 0..63
        wp[i] = wo + m * 288;
        bias[i] = bo[m];
    }

    unsigned long long acc[4][4];
#pragma unroll
    for (int i = 0; i < 4; i++)
#pragma unroll
        for (int r = 0; r < 4; r++) acc[i][r] = pk2(bias[i], bias[i]);

    const int c0 = tn * 2;

    for (int ic = 0; ic < 32; ic++) {
        const float* xr = &Xs[ic * 192];
        unsigned long long pL[6], pC[6], pR[6];
#pragma unroll
        for (int r = 0; r < 6; r++) {
            float x0 = xr[r * 32 + c0];
            float x1 = xr[r * 32 + c0 + 1];
            float xm = (c0 > 0)  ? xr[r * 32 + c0 - 1] : 0.f;
            float x2 = (c0 < 30) ? xr[r * 32 + c0 + 2] : 0.f;
            pL[r] = pk2(xm, x0);
            pC[r] = pk2(x0, x1);
            pR[r] = pk2(x1, x2);
        }
#pragma unroll
        for (int dh = 0; dh < 3; dh++) {
#pragma unroll
            for (int dw = 0; dw < 3; dw++) {
#pragma unroll
                for (int i = 0; i < 4; i++) {
                    float w = wp[i][ic * 9 + dh * 3 + dw];
                    unsigned long long wpk = pk2(w, w);
#pragma unroll
                    for (int r = 0; r < 4; r++) {
                        unsigned long long xv = (dw == 0) ? pL[r + dh]
                                              : (dw == 1) ? pC[r + dh]
                                                          : pR[r + dh];
                        fma2(acc[i][r], xv, wpk);
                    }
                }
            }
        }
    }

#pragma unroll
    for (int i = 0; i < 4; i++) {
        int m = tm * 4 + i;
        float* p = out + ((size_t)(b * 64 + m) * 64 + s) * 1024 + h0 * 32 + c0;
#pragma unroll
        for (int r = 0; r < 4; r++) {
            *(float2*)(p + r * 32) = up2(acc[i][r]);
        }
    }
}

// ---------------------------------------------------------------------------
// kernel_launch
// ---------------------------------------------------------------------------
extern "C" void kernel_launch(void* const* d_in, const int* in_sizes, int n_in,
                              void* d_out, int out_size) {
    const float* x  = (const float*)d_in[0];
    const float* wq = (const float*)d_in[1];
    const float* bq = (const float*)d_in[2];
    const float* wk = (const float*)d_in[3];
    const float* bk = (const float*)d_in[4];
    const float* wv = (const float*)d_in[5];
    const float* bv = (const float*)d_in[6];
    const float* wo = (const float*)d_in[7];
    const float* bo = (const float*)d_in[8];
    float* out = (float*)d_out;

    dim3 cgrid(8, 64, 16);   // (h-strip, s, b)
    qkv_conv_kernel<<<cgrid, 256>>>(x, wq, bq, wk, bk, wv, bv);
    attn_kernel<<<512, 256>>>();
    oconv_kernel<<<cgrid, 256>>>(wo, bo, out);
}

// round 2
// speedup vs baseline: 1.1087x; 1.1087x over previous
#include <cuda_runtime.h>

typedef unsigned long long ull;

// ---------------------------------------------------------------------------
// Scratch (device-global; no allocations allowed)
// ---------------------------------------------------------------------------
static __device__ float g_q [33554432];
static __device__ float g_k [33554432];
static __device__ float g_v [33554432];
static __device__ float g_ao[33554432];

// duplicated (w,w) weight pairs, padded to 10 taps per (m,ic) for 16B alignment
static __device__ __align__(16) ull g_wqkv_pk[96 * 64 * 10];   // 480 KB
static __device__ __align__(16) ull g_wo_pk  [64 * 32 * 10];   // 160 KB

// ---------------------------------------------------------------------------
// Packed fp32x2 helpers (FFMA2 is PTX-only)
// ---------------------------------------------------------------------------
__device__ __forceinline__ ull pk2(float lo, float hi) {
    ull r;
    asm("mov.b64 %0, {%1, %2};" : "=l"(r) : "f"(lo), "f"(hi));
    return r;
}
__device__ __forceinline__ void fma2(ull& d, ull a, ull b) {
    asm("fma.rn.f32x2 %0, %1, %2, %0;" : "+l"(d) : "l"(a), "l"(b));
}

// ---------------------------------------------------------------------------
// Weight pre-pack: w -> (w,w) 64-bit pairs, [m][ic][10] layout
// ---------------------------------------------------------------------------
__global__ void pack_weights(const float* __restrict__ wq,
                             const float* __restrict__ wk,
                             const float* __restrict__ wv,
                             const float* __restrict__ wo)
{
    int i = blockIdx.x * 256 + threadIdx.x;
    const int NQKV = 96 * 64 * 10;
    if (i < NQKV) {
        int m = i / 640, rem = i - m * 640;
        int ic = rem / 10, t = rem - ic * 10;
        float w = 0.f;
        if (t < 9) {
            const float* src = (m < 32) ? wq + m * 576
                             : (m < 64) ? wk + (m - 32) * 576
                                        : wv + (m - 64) * 576;
            w = src[ic * 9 + t];
        }
        unsigned u = __float_as_uint(w);
        g_wqkv_pk[i] = ((ull)u << 32) | u;
    } else {
        int j = i - NQKV;
        if (j < 64 * 32 * 10) {
            int m = j / 320, rem = j - m * 320;
            int ic = rem / 10, t = rem - ic * 10;
            float w = (t < 9) ? wo[m * 288 + ic * 9 + t] : 0.f;
            unsigned u = __float_as_uint(w);
            g_wo_pk[j] = ((ull)u << 32) | u;
        }
    }
}

// ---------------------------------------------------------------------------
// Kernel 1: fused q/k/v conv (1x3x3, pad (1,1)).
// Grid (8,64,16). Block 256. Block: 96 out-ch x (4 rows x 32 cols).
// Thread: 6 out-ch x 4 row-pairs (f32x2 along W). ic processed in 2 chunks.
// smem row layout: 34 floats, col c at index c+1, idx 0/33 = zero border.
// ---------------------------------------------------------------------------
__global__ __launch_bounds__(256, 2) void qkv_conv_kernel(
    const float* __restrict__ x,
    const float* __restrict__ bq, const float* __restrict__ bk,
    const float* __restrict__ bv)
{
    __shared__ float Xs[32 * 6 * 34];     // 26.1 KB per chunk

    const int strip = blockIdx.x;
    const int s     = blockIdx.y;
    const int b     = blockIdx.z;
    const int tid   = threadIdx.x;
    const int tm    = tid >> 4;
    const int tn    = tid & 15;
    const int h0    = strip * 4;
    const int c0    = tn * 2;
    const int m0    = tm * 6;

    ull acc[6][4];
#pragma unroll
    for (int i = 0; i < 6; i++) {
        int m = m0 + i;
        float bv_ = (m < 32) ? bq[m] : (m < 64) ? bk[m - 32] : bv[m - 64];
        ull p = pk2(bv_, bv_);
#pragma unroll
        for (int r = 0; r < 4; r++) acc[i][r] = p;
    }

    for (int chk = 0; chk < 2; chk++) {
        if (chk) __syncthreads();
        const float* xb = x + (((size_t)b * 64 + chk * 32) * 64 + s) * 1024;
        for (int idx = tid; idx < 32 * 6 * 34; idx += 256) {
            int ic  = idx / 204;
            int rem = idx - ic * 204;
            int r   = rem / 34;
            int c   = rem - r * 34;
            int gh  = h0 - 1 + r;
            float v = 0.f;
            if (c >= 1 && c <= 32 && gh >= 0 && gh < 32)
                v = xb[ic * 65536 + gh * 32 + (c - 1)];
            Xs[idx] = v;
        }
        __syncthreads();

        for (int ic = 0; ic < 32; ic++) {
            const float* xr = &Xs[ic * 204 + c0];
            ull A[6], C[6], Bp[6];       // (x-1,x0), (x1,x2), (x0,x1)
#pragma unroll
            for (int r = 0; r < 6; r++) {
                A[r] = *(const ull*)(xr + r * 34);
                C[r] = *(const ull*)(xr + r * 34 + 2);
                float x0 = xr[r * 34 + 1];
                float x1 = xr[r * 34 + 2];
                Bp[r] = pk2(x0, x1);
            }
            const int icg = chk * 32 + ic;
#pragma unroll
            for (int i = 0; i < 6; i++) {
                const ulonglong2* wp =
                    (const ulonglong2*)(g_wqkv_pk + ((size_t)(m0 + i) * 64 + icg) * 10);
                ulonglong2 wA = wp[0];   // taps 0,1
                ulonglong2 wB = wp[1];   // taps 2,3
                ulonglong2 wC = wp[2];   // taps 4,5
                ulonglong2 wD = wp[3];   // taps 6,7
                ull w8 = ((const ull*)wp)[8];
#pragma unroll
                for (int r = 0; r < 4; r++) {
                    fma2(acc[i][r], A [r + 0], wA.x);
                    fma2(acc[i][r], Bp[r + 0], wA.y);
                    fma2(acc[i][r], C [r + 0], wB.x);
                    fma2(acc[i][r], A [r + 1], wB.y);
                    fma2(acc[i][r], Bp[r + 1], wC.x);
                    fma2(acc[i][r], C [r + 1], wC.y);
                    fma2(acc[i][r], A [r + 2], wD.x);
                    fma2(acc[i][r], Bp[r + 2], wD.y);
                    fma2(acc[i][r], C [r + 2], w8);
                }
            }
        }
    }

#pragma unroll
    for (int i = 0; i < 6; i++) {
        int m = m0 + i;
        float* dst = (m < 32) ? g_q : (m < 64) ? g_k : g_v;
        int ch = m & 31;
        float* p = dst + ((size_t)(b * 32 + ch) * 64 + s) * 1024 + h0 * 32 + c0;
#pragma unroll
        for (int r = 0; r < 4; r++)
            *(ull*)(p + r * 32) = acc[i][r];
    }
}

// ---------------------------------------------------------------------------
// Kernel 2: per-(b,c) attention. 512 blocks x 256 threads.
// ---------------------------------------------------------------------------
__global__ __launch_bounds__(256) void attn_kernel()
{
    __shared__ float A[64 * 64];
    __shared__ float Buf[4224];

    const int bc  = blockIdx.x;
    const float* q = g_q + (size_t)bc * 65536;
    const float* k = g_k + (size_t)bc * 65536;
    const float* v = g_v + (size_t)bc * 65536;
    float*       o = g_ao + (size_t)bc * 65536;

    const int tid = threadIdx.x;
    const int ty  = tid >> 4;
    const int tx  = tid & 15;

    float* Qs = Buf;
    float* Ks = Buf + 2112;

    float sc[4][4];
#pragma unroll
    for (int a = 0; a < 4; a++)
#pragma unroll
        for (int c = 0; c < 4; c++) sc[a][c] = 0.f;

    for (int f0 = 0; f0 < 1024; f0 += 32) {
#pragma unroll
        for (int i = 0; i < 8; i++) {
            int idx = tid + i * 256;
            int row = idx >> 5, col = idx & 31;
            Qs[row * 33 + col] = q[row * 1024 + f0 + col];
            Ks[row * 33 + col] = k[row * 1024 + f0 + col];
        }
        __syncthreads();
#pragma unroll
        for (int ff = 0; ff < 32; ff++) {
            float qv[4], kv[4];
#pragma unroll
            for (int u = 0; u < 4; u++) qv[u] = Qs[(ty + 16 * u) * 33 + ff];
#pragma unroll
            for (int u = 0; u < 4; u++) kv[u] = Ks[(tx + 16 * u) * 33 + ff];
#pragma unroll
            for (int us = 0; us < 4; us++)
#pragma unroll
                for (int ut = 0; ut < 4; ut++)
                    sc[us][ut] = fmaf(qv[us], kv[ut], sc[us][ut]);
        }
        __syncthreads();
    }
    const float scale = 0.03125f;
#pragma unroll
    for (int us = 0; us < 4; us++)
#pragma unroll
        for (int ut = 0; ut < 4; ut++) {
            float z = sc[us][ut] * scale;
            A[(ty + 16 * us) * 64 + (tx + 16 * ut)] = 1.f / (1.f + __expf(-z));
        }
    __syncthreads();

    float* Vs = Buf;
    for (int f0 = 0; f0 < 1024; f0 += 64) {
#pragma unroll
        for (int i = 0; i < 16; i++) {
            int idx = tid + i * 256;
            int row = idx >> 6, col = idx & 63;
            Vs[row * 65 + col] = v[row * 1024 + f0 + col];
        }
        __syncthreads();
        float oacc[4][4];
#pragma unroll
        for (int a = 0; a < 4; a++)
#pragma unroll
            for (int c = 0; c < 4; c++) oacc[a][c] = 0.f;
        for (int t = 0; t < 64; t++) {
            float av[4], vv[4];
#pragma unroll
            for (int u = 0; u < 4; u++) av[u] = A[(ty + 16 * u) * 64 + t];
#pragma unroll
            for (int u = 0; u < 4; u++) vv[u] = Vs[t * 65 + tx + 16 * u];
#pragma unroll
            for (int us = 0; us < 4; us++)
#pragma unroll
                for (int uf = 0; uf < 4; uf++)
                    oacc[us][uf] = fmaf(av[us], vv[uf], oacc[us][uf]);
        }
#pragma unroll
        for (int us = 0; us < 4; us++)
#pragma unroll
            for (int uf = 0; uf < 4; uf++)
                o[(ty + 16 * us) * 1024 + f0 + tx + 16 * uf] = oacc[us][uf];
        __syncthreads();
    }
}

// ---------------------------------------------------------------------------
// Kernel 3: output conv (32 -> 64), same structure, single ic chunk.
// ---------------------------------------------------------------------------
__global__ __launch_bounds__(256, 2) void oconv_kernel(
    const float* __restrict__ bo, float* __restrict__ out)
{
    __shared__ float Xs[32 * 6 * 34];

    const int strip = blockIdx.x;
    const int s     = blockIdx.y;
    const int b     = blockIdx.z;
    const int tid   = threadIdx.x;
    const int tm    = tid >> 4;
    const int tn    = tid & 15;
    const int h0    = strip * 4;
    const int c0    = tn * 2;
    const int m0    = tm * 4;

    ull acc[4][4];
#pragma unroll
    for (int i = 0; i < 4; i++) {
        float bv_ = bo[m0 + i];
        ull p = pk2(bv_, bv_);
#pragma unroll
        for (int r = 0; r < 4; r++) acc[i][r] = p;
    }

    const float* xb = g_ao + ((size_t)(b * 32) * 64 + s) * 1024;
    for (int idx = tid; idx < 32 * 6 * 34; idx += 256) {
        int ic  = idx / 204;
        int rem = idx - ic * 204;
        int r   = rem / 34;
        int c   = rem - r * 34;
        int gh  = h0 - 1 + r;
        float v = 0.f;
        if (c >= 1 && c <= 32 && gh >= 0 && gh < 32)
            v = xb[ic * 65536 + gh * 32 + (c - 1)];
        Xs[idx] = v;
    }
    __syncthreads();

    for (int ic = 0; ic < 32; ic++) {
        const float* xr = &Xs[ic * 204 + c0];
        ull A[6], C[6], Bp[6];
#pragma unroll
        for (int r = 0; r < 6; r++) {
            A[r] = *(const ull*)(xr + r * 34);
            C[r] = *(const ull*)(xr + r * 34 + 2);
            float x0 = xr[r * 34 + 1];
            float x1 = xr[r * 34 + 2];
            Bp[r] = pk2(x0, x1);
        }
#pragma unroll
        for (int i = 0; i < 4; i++) {
            const ulonglong2* wp =
                (const ulonglong2*)(g_wo_pk + ((size_t)(m0 + i) * 32 + ic) * 10);
            ulonglong2 wA = wp[0];
            ulonglong2 wB = wp[1];
            ulonglong2 wC = wp[2];
            ulonglong2 wD = wp[3];
            ull w8 = ((const ull*)wp)[8];
#pragma unroll
            for (int r = 0; r < 4; r++) {
                fma2(acc[i][r], A [r + 0], wA.x);
                fma2(acc[i][r], Bp[r + 0], wA.y);
                fma2(acc[i][r], C [r + 0], wB.x);
                fma2(acc[i][r], A [r + 1], wB.y);
                fma2(acc[i][r], Bp[r + 1], wC.x);
                fma2(acc[i][r], C [r + 1], wC.y);
                fma2(acc[i][r], A [r + 2], wD.x);
                fma2(acc[i][r], Bp[r + 2], wD.y);
                fma2(acc[i][r], C [r + 2], w8);
            }
        }
    }

#pragma unroll
    for (int i = 0; i < 4; i++) {
        int m = m0 + i;
        float* p = out + ((size_t)(b * 64 + m) * 64 + s) * 1024 + h0 * 32 + c0;
#pragma unroll
        for (int r = 0; r < 4; r++)
            *(ull*)(p + r * 32) = acc[i][r];
    }
}

// ---------------------------------------------------------------------------
// kernel_launch
// ---------------------------------------------------------------------------
extern "C" void kernel_launch(void* const* d_in, const int* in_sizes, int n_in,
                              void* d_out, int out_size) {
    const float* x  = (const float*)d_in[0];
    const float* wq = (const float*)d_in[1];
    const float* bq = (const float*)d_in[2];
    const float* wk = (const float*)d_in[3];
    const float* bk = (const float*)d_in[4];
    const float* wv = (const float*)d_in[5];
    const float* bv = (const float*)d_in[6];
    const float* wo = (const float*)d_in[7];
    const float* bo = (const float*)d_in[8];
    float* out = (float*)d_out;

    pack_weights<<<320, 256>>>(wq, wk, wv, wo);

    dim3 cgrid(8, 64, 16);
    qkv_conv_kernel<<<cgrid, 256>>>(x, bq, bk, bv);
    attn_kernel<<<512, 256>>>();
    oconv_kernel<<<cgrid, 256>>>(bo, out);
}

// round 4
// speedup vs baseline: 1.1097x; 1.0009x over previous
#include <cuda_runtime.h>

typedef unsigned long long ull;

// ---------------------------------------------------------------------------
// Scratch (device-global; no allocations allowed)
// ---------------------------------------------------------------------------
static __device__ float g_q [33554432];
static __device__ float g_k [33554432];
static __device__ float g_v [33554432];
static __device__ float g_ao[33554432];

// duplicated (w,w) weight pairs, padded to 10 taps per (m,ic) for 16B alignment
static __device__ __align__(16) ull g_wqkv_pk[96 * 64 * 10];   // 480 KB
static __device__ __align__(16) ull g_wo_pk  [64 * 32 * 10];   // 160 KB

// ---------------------------------------------------------------------------
// Packed fp32x2 helpers (FFMA2 is PTX-only)
// ---------------------------------------------------------------------------
__device__ __forceinline__ ull pk2(float lo, float hi) {
    ull r;
    asm("mov.b64 %0, {%1, %2};" : "=l"(r) : "f"(lo), "f"(hi));
    return r;
}
__device__ __forceinline__ void fma2(ull& d, ull a, ull b) {
    asm("fma.rn.f32x2 %0, %1, %2, %0;" : "+l"(d) : "l"(a), "l"(b));
}

// ---------------------------------------------------------------------------
// Weight pre-pack: w -> (w,w) 64-bit pairs, [m][ic][10] layout
// ---------------------------------------------------------------------------
__global__ void pack_weights(const float* __restrict__ wq,
                             const float* __restrict__ wk,
                             const float* __restrict__ wv,
                             const float* __restrict__ wo)
{
    int i = blockIdx.x * 256 + threadIdx.x;
    const int NQKV = 96 * 64 * 10;
    if (i < NQKV) {
        int m = i / 640, rem = i - m * 640;
        int ic = rem / 10, t = rem - ic * 10;
        float w = 0.f;
        if (t < 9) {
            const float* src = (m < 32) ? wq + m * 576
                             : (m < 64) ? wk + (m - 32) * 576
                                        : wv + (m - 64) * 576;
            w = src[ic * 9 + t];
        }
        unsigned u = __float_as_uint(w);
        g_wqkv_pk[i] = ((ull)u << 32) | u;
    } else {
        int j = i - NQKV;
        if (j < 64 * 32 * 10) {
            int m = j / 320, rem = j - m * 320;
            int ic = rem / 10, t = rem - ic * 10;
            float w = (t < 9) ? wo[m * 288 + ic * 9 + t] : 0.f;
            unsigned u = __float_as_uint(w);
            g_wo_pk[j] = ((ull)u << 32) | u;
        }
    }
}

// ---------------------------------------------------------------------------
// Kernel 1: fused q/k/v conv (1x3x3, pad (1,1)).
// Grid (8,64,16). Block 256. Block: 96 out-ch x (4 rows x 32 cols).
// Thread: 6 out-ch x 4 row-pairs (f32x2 along W). ic processed in 2 chunks.
// smem row layout: 34 floats, col c at index c+1, idx 0/33 = zero border.
// ---------------------------------------------------------------------------
__global__ __launch_bounds__(256, 2) void qkv_conv_kernel(
    const float* __restrict__ x,
    const float* __restrict__ bq, const float* __restrict__ bk,
    const float* __restrict__ bv)
{
    __shared__ float Xs[32 * 6 * 34];     // 26.1 KB per chunk

    const int strip = blockIdx.x;
    const int s     = blockIdx.y;
    const int b     = blockIdx.z;
    const int tid   = threadIdx.x;
    const int tm    = tid >> 4;
    const int tn    = tid & 15;
    const int h0    = strip * 4;
    const int c0    = tn * 2;
    const int m0    = tm * 6;

    ull acc[6][4];
#pragma unroll
    for (int i = 0; i < 6; i++) {
        int m = m0 + i;
        float bv_ = (m < 32) ? bq[m] : (m < 64) ? bk[m - 32] : bv[m - 64];
        ull p = pk2(bv_, bv_);
#pragma unroll
        for (int r = 0; r < 4; r++) acc[i][r] = p;
    }

    for (int chk = 0; chk < 2; chk++) {
        if (chk) __syncthreads();
        const float* xb = x + (((size_t)b * 64 + chk * 32) * 64 + s) * 1024;
        for (int idx = tid; idx < 32 * 6 * 34; idx += 256) {
            int ic  = idx / 204;
            int rem = idx - ic * 204;
            int r   = rem / 34;
            int c   = rem - r * 34;
            int gh  = h0 - 1 + r;
            float v = 0.f;
            if (c >= 1 && c <= 32 && gh >= 0 && gh < 32)
                v = xb[ic * 65536 + gh * 32 + (c - 1)];
            Xs[idx] = v;
        }
        __syncthreads();

        for (int ic = 0; ic < 32; ic++) {
            const float* xr = &Xs[ic * 204 + c0];
            ull A[6], C[6], Bp[6];       // (x-1,x0), (x1,x2), (x0,x1)
#pragma unroll
            for (int r = 0; r < 6; r++) {
                A[r] = *(const ull*)(xr + r * 34);
                C[r] = *(const ull*)(xr + r * 34 + 2);
                float x0 = xr[r * 34 + 1];
                float x1 = xr[r * 34 + 2];
                Bp[r] = pk2(x0, x1);
            }
            const int icg = chk * 32 + ic;
#pragma unroll
            for (int i = 0; i < 6; i++) {
                const ulonglong2* wp =
                    (const ulonglong2*)(g_wqkv_pk + ((size_t)(m0 + i) * 64 + icg) * 10);
                ulonglong2 wA = wp[0];   // taps 0,1
                ulonglong2 wB = wp[1];   // taps 2,3
                ulonglong2 wC = wp[2];   // taps 4,5
                ulonglong2 wD = wp[3];   // taps 6,7
                ull w8 = ((const ull*)wp)[8];
#pragma unroll
                for (int r = 0; r < 4; r++) {
                    fma2(acc[i][r], A [r + 0], wA.x);
                    fma2(acc[i][r], Bp[r + 0], wA.y);
                    fma2(acc[i][r], C [r + 0], wB.x);
                    fma2(acc[i][r], A [r + 1], wB.y);
                    fma2(acc[i][r], Bp[r + 1], wC.x);
                    fma2(acc[i][r], C [r + 1], wC.y);
                    fma2(acc[i][r], A [r + 2], wD.x);
                    fma2(acc[i][r], Bp[r + 2], wD.y);
                    fma2(acc[i][r], C [r + 2], w8);
                }
            }
        }
    }

#pragma unroll
    for (int i = 0; i < 6; i++) {
        int m = m0 + i;
        float* dst = (m < 32) ? g_q : (m < 64) ? g_k : g_v;
        int ch = m & 31;
        float* p = dst + ((size_t)(b * 32 + ch) * 64 + s) * 1024 + h0 * 32 + c0;
#pragma unroll
        for (int r = 0; r < 4; r++)
            *(ull*)(p + r * 32) = acc[i][r];
    }
}

// ---------------------------------------------------------------------------
// Kernel 2: per-(b,c) attention. 512 blocks x 256 threads.
// ---------------------------------------------------------------------------
__global__ __launch_bounds__(256) void attn_kernel()
{
    __shared__ float A[64 * 64];
    __shared__ float Buf[4224];

    const int bc  = blockIdx.x;
    const float* q = g_q + (size_t)bc * 65536;
    const float* k = g_k + (size_t)bc * 65536;
    const float* v = g_v + (size_t)bc * 65536;
    float*       o = g_ao + (size_t)bc * 65536;

    const int tid = threadIdx.x;
    const int ty  = tid >> 4;
    const int tx  = tid & 15;

    float* Qs = Buf;
    float* Ks = Buf + 2112;

    float sc[4][4];
#pragma unroll
    for (int a = 0; a < 4; a++)
#pragma unroll
        for (int c = 0; c < 4; c++) sc[a][c] = 0.f;

    for (int f0 = 0; f0 < 1024; f0 += 32) {
#pragma unroll
        for (int i = 0; i < 8; i++) {
            int idx = tid + i * 256;
            int row = idx >> 5, col = idx & 31;
            Qs[row * 33 + col] = q[row * 1024 + f0 + col];
            Ks[row * 33 + col] = k[row * 1024 + f0 + col];
        }
        __syncthreads();
#pragma unroll
        for (int ff = 0; ff < 32; ff++) {
            float qv[4], kv[4];
#pragma unroll
            for (int u = 0; u < 4; u++) qv[u] = Qs[(ty + 16 * u) * 33 + ff];
#pragma unroll
            for (int u = 0; u < 4; u++) kv[u] = Ks[(tx + 16 * u) * 33 + ff];
#pragma unroll
            for (int us = 0; us < 4; us++)
#pragma unroll
                for (int ut = 0; ut < 4; ut++)
                    sc[us][ut] = fmaf(qv[us], kv[ut], sc[us][ut]);
        }
        __syncthreads();
    }
    const float scale = 0.03125f;
#pragma unroll
    for (int us = 0; us < 4; us++)
#pragma unroll
        for (int ut = 0; ut < 4; ut++) {
            float z = sc[us][ut] * scale;
            A[(ty + 16 * us) * 64 + (tx + 16 * ut)] = 1.f / (1.f + __expf(-z));
        }
    __syncthreads();

    float* Vs = Buf;
    for (int f0 = 0; f0 < 1024; f0 += 64) {
#pragma unroll
        for (int i = 0; i < 16; i++) {
            int idx = tid + i * 256;
            int row = idx >> 6, col = idx & 63;
            Vs[row * 65 + col] = v[row * 1024 + f0 + col];
        }
        __syncthreads();
        float oacc[4][4];
#pragma unroll
        for (int a = 0; a < 4; a++)
#pragma unroll
            for (int c = 0; c < 4; c++) oacc[a][c] = 0.f;
        for (int t = 0; t < 64; t++) {
            float av[4], vv[4];
#pragma unroll
            for (int u = 0; u < 4; u++) av[u] = A[(ty + 16 * u) * 64 + t];
#pragma unroll
            for (int u = 0; u < 4; u++) vv[u] = Vs[t * 65 + tx + 16 * u];
#pragma unroll
            for (int us = 0; us < 4; us++)
#pragma unroll
                for (int uf = 0; uf < 4; uf++)
                    oacc[us][uf] = fmaf(av[us], vv[uf], oacc[us][uf]);
        }
#pragma unroll
        for (int us = 0; us < 4; us++)
#pragma unroll
            for (int uf = 0; uf < 4; uf++)
                o[(ty + 16 * us) * 1024 + f0 + tx + 16 * uf] = oacc[us][uf];
        __syncthreads();
    }
}

// ---------------------------------------------------------------------------
// Kernel 3: output conv (32 -> 64), same structure, single ic chunk.
// ---------------------------------------------------------------------------
__global__ __launch_bounds__(256, 2) void oconv_kernel(
    const float* __restrict__ bo, float* __restrict__ out)
{
    __shared__ float Xs[32 * 6 * 34];

    const int strip = blockIdx.x;
    const int s     = blockIdx.y;
    const int b     = blockIdx.z;
    const int tid   = threadIdx.x;
    const int tm    = tid >> 4;
    const int tn    = tid & 15;
    const int h0    = strip * 4;
    const int c0    = tn * 2;
    const int m0    = tm * 4;

    ull acc[4][4];
#pragma unroll
    for (int i = 0; i < 4; i++) {
        float bv_ = bo[m0 + i];
        ull p = pk2(bv_, bv_);
#pragma unroll
        for (int r = 0; r < 4; r++) acc[i][r] = p;
    }

    const float* xb = g_ao + ((size_t)(b * 32) * 64 + s) * 1024;
    for (int idx = tid; idx < 32 * 6 * 34; idx += 256) {
        int ic  = idx / 204;
        int rem = idx - ic * 204;
        int r   = rem / 34;
        int c   = rem - r * 34;
        int gh  = h0 - 1 + r;
        float v = 0.f;
        if (c >= 1 && c <= 32 && gh >= 0 && gh < 32)
            v = xb[ic * 65536 + gh * 32 + (c - 1)];
        Xs[idx] = v;
    }
    __syncthreads();

    for (int ic = 0; ic < 32; ic++) {
        const float* xr = &Xs[ic * 204 + c0];
        ull A[6], C[6], Bp[6];
#pragma unroll
        for (int r = 0; r < 6; r++) {
            A[r] = *(const ull*)(xr + r * 34);
            C[r] = *(const ull*)(xr + r * 34 + 2);
            float x0 = xr[r * 34 + 1];
            float x1 = xr[r * 34 + 2];
            Bp[r] = pk2(x0, x1);
        }
#pragma unroll
        for (int i = 0; i < 4; i++) {
            const ulonglong2* wp =
                (const ulonglong2*)(g_wo_pk + ((size_t)(m0 + i) * 32 + ic) * 10);
            ulonglong2 wA = wp[0];
            ulonglong2 wB = wp[1];
            ulonglong2 wC = wp[2];
            ulonglong2 wD = wp[3];
            ull w8 = ((const ull*)wp)[8];
#pragma unroll
            for (int r = 0; r < 4; r++) {
                fma2(acc[i][r], A [r + 0], wA.x);
                fma2(acc[i][r], Bp[r + 0], wA.y);
                fma2(acc[i][r], C [r + 0], wB.x);
                fma2(acc[i][r], A [r + 1], wB.y);
                fma2(acc[i][r], Bp[r + 1], wC.x);
                fma2(acc[i][r], C [r + 1], wC.y);
                fma2(acc[i][r], A [r + 2], wD.x);
                fma2(acc[i][r], Bp[r + 2], wD.y);
                fma2(acc[i][r], C [r + 2], w8);
            }
        }
    }

#pragma unroll
    for (int i = 0; i < 4; i++) {
        int m = m0 + i;
        float* p = out + ((size_t)(b * 64 + m) * 64 + s) * 1024 + h0 * 32 + c0;
#pragma unroll
        for (int r = 0; r < 4; r++)
            *(ull*)(p + r * 32) = acc[i][r];
    }
}

// ---------------------------------------------------------------------------
// kernel_launch
// ---------------------------------------------------------------------------
extern "C" void kernel_launch(void* const* d_in, const int* in_sizes, int n_in,
                              void* d_out, int out_size) {
    const float* x  = (const float*)d_in[0];
    const float* wq = (const float*)d_in[1];
    const float* bq = (const float*)d_in[2];
    const float* wk = (const float*)d_in[3];
    const float* bk = (const float*)d_in[4];
    const float* wv = (const float*)d_in[5];
    const float* bv = (const float*)d_in[6];
    const float* wo = (const float*)d_in[7];
    const float* bo = (const float*)d_in[8];
    float* out = (float*)d_out;

    pack_weights<<<320, 256>>>(wq, wk, wv, wo);

    dim3 cgrid(8, 64, 16);
    qkv_conv_kernel<<<cgrid, 256>>>(x, bq, bk, bv);
    attn_kernel<<<512, 256>>>();
    oconv_kernel<<<cgrid, 256>>>(bo, out);
}

// round 8
// speedup vs baseline: 2.9568x; 2.6646x over previous
#include <cuda_runtime.h>
#include <cuda_bf16.h>

typedef unsigned long long ull;
typedef unsigned int u32;

// ---------------------------------------------------------------------------
// Scratch
// ---------------------------------------------------------------------------
static __device__ float g_q [33554432];
static __device__ float g_k [33554432];
static __device__ float g_v [33554432];
static __device__ float g_ao[33554432];

// B fragments, prepacked in mma.sync fragment order.
// qkv: [tap 9][ks 4][n8 12][lane 32] x uint4 {bhi0,bhi1,blo0,blo1}
static __device__ __align__(16) uint4 g_Bfq[9 * 4 * 12 * 32];
// oconv: [tap 9][ks 2][n8 8][lane 32] x uint4
static __device__ __align__(16) uint4 g_Bfo[9 * 2 * 8 * 32];

// ---------------------------------------------------------------------------
// helpers
// ---------------------------------------------------------------------------
__device__ __forceinline__ u32 smem_u32(const void* p) {
    u32 a;
    asm("{ .reg .u64 t; cvta.to.shared.u64 t, %1; cvt.u32.u64 %0, t; }" : "=r"(a) : "l"(p));
    return a;
}
__device__ __forceinline__ unsigned short us_of(__nv_bfloat16 h) {
    return *reinterpret_cast<unsigned short*>(&h);
}
__device__ __forceinline__ void ldsm4(u32* r, u32 addr) {
    asm volatile("ldmatrix.sync.aligned.m8n8.x4.shared.b16 {%0,%1,%2,%3}, [%4];"
                 : "=r"(r[0]), "=r"(r[1]), "=r"(r[2]), "=r"(r[3]) : "r"(addr));
}
__device__ __forceinline__ void mma_bf16(float* c, const u32* a, u32 b0, u32 b1) {
    asm volatile(
        "mma.sync.aligned.m16n8k16.row.col.f32.bf16.bf16.f32 "
        "{%0,%1,%2,%3}, {%4,%5,%6,%7}, {%8,%9}, {%0,%1,%2,%3};"
        : "+f"(c[0]), "+f"(c[1]), "+f"(c[2]), "+f"(c[3])
        : "r"(a[0]), "r"(a[1]), "r"(a[2]), "r"(a[3]), "r"(b0), "r"(b1));
}

// ---------------------------------------------------------------------------
// Weight fragment pre-pack
// ---------------------------------------------------------------------------
__global__ void pack_qkv_frag(const float* __restrict__ wq, const float* __restrict__ wk,
                              const float* __restrict__ wv)
{
    int idx = blockIdx.x * 256 + threadIdx.x;
    if (idx >= 9 * 4 * 12 * 32) return;
    int lane = idx & 31; int t = idx >> 5;
    int n8 = t % 12; t /= 12;
    int ks = t & 3;  int tap = t >> 2;
    int dh = tap / 3, dw = tap % 3;
    int n = n8 * 8 + (lane >> 2);
    const float* src = (n < 32) ? wq + n * 576
                     : (n < 64) ? wk + (n - 32) * 576
                                : wv + (n - 64) * 576;
    u32 u[4];
#pragma unroll
    for (int r = 0; r < 2; r++) {
        int ic0 = ks * 16 + r * 8 + (lane & 3) * 2;
        float w0 = src[ic0 * 9 + dh * 3 + dw];
        float w1 = src[(ic0 + 1) * 9 + dh * 3 + dw];
        __nv_bfloat16 h0 = __float2bfloat16(w0), h1 = __float2bfloat16(w1);
        __nv_bfloat16 l0 = __float2bfloat16(w0 - __bfloat162float(h0));
        __nv_bfloat16 l1 = __float2bfloat16(w1 - __bfloat162float(h1));
        u[r]     = (u32)us_of(h0) | ((u32)us_of(h1) << 16);
        u[2 + r] = (u32)us_of(l0) | ((u32)us_of(l1) << 16);
    }
    g_Bfq[idx] = make_uint4(u[0], u[1], u[2], u[3]);
}

__global__ void pack_o_frag(const float* __restrict__ wo)
{
    int idx = blockIdx.x * 256 + threadIdx.x;
    if (idx >= 9 * 2 * 8 * 32) return;
    int lane = idx & 31; int t = idx >> 5;
    int n8 = t & 7; t >>= 3;
    int ks = t & 1;  int tap = t >> 1;
    int dh = tap / 3, dw = tap % 3;
    int n = n8 * 8 + (lane >> 2);
    const float* src = wo + n * 288;
    u32 u[4];
#pragma unroll
    for (int r = 0; r < 2; r++) {
        int ic0 = ks * 16 + r * 8 + (lane & 3) * 2;
        float w0 = src[ic0 * 9 + dh * 3 + dw];
        float w1 = src[(ic0 + 1) * 9 + dh * 3 + dw];
        __nv_bfloat16 h0 = __float2bfloat16(w0), h1 = __float2bfloat16(w1);
        __nv_bfloat16 l0 = __float2bfloat16(w0 - __bfloat162float(h0));
        __nv_bfloat16 l1 = __float2bfloat16(w1 - __bfloat162float(h1));
        u[r]     = (u32)us_of(h0) | ((u32)us_of(h1) << 16);
        u[2 + r] = (u32)us_of(l0) | ((u32)us_of(l1) << 16);
    }
    g_Bfo[idx] = make_uint4(u[0], u[1], u[2], u[3]);
}

// ---------------------------------------------------------------------------
// qkv conv via mma.sync bf16 3-pass.
// Grid (8,64,16), block 256 (8 warps: warpM = wid>>2 in {0,1}, warpN = wid&3).
// Block tile: M=128 pixels x N=96. Warp tile: 64 x 24 (4 m16 x 3 n8).
// smem: Xhi/Xlo [6h][34w][72 ic-pad] bf16; epilogue staging [96][132] f32.
// ---------------------------------------------------------------------------
#define QKV_SMEM 58752

__global__ __launch_bounds__(256, 2) void qkv_mma(
    const float* __restrict__ x,
    const float* __restrict__ bq, const float* __restrict__ bk,
    const float* __restrict__ bv)
{
    extern __shared__ __align__(16) unsigned char sm[];
    unsigned short* Xhi = (unsigned short*)sm;           // 14688 elems
    unsigned short* Xlo = Xhi + 14688;
    const int strip = blockIdx.x, s = blockIdx.y, b = blockIdx.z;
    const int tid = threadIdx.x;
    const int wid = tid >> 5, lane = tid & 31;
    const int warpM = wid >> 2, warpN = wid & 3;
    const u32 sb = smem_u32(sm);

    // ---- halo fill: (ic, h, w), w fastest for coalescing ----
    for (int i = tid; i < 6 * 34 * 64; i += 256) {
        int ic = i / 204; int rem = i - ic * 204;
        int h = rem / 34, w = rem - h * 34;
        int gh = strip * 4 + h - 1, wi = w - 1;
        float v = 0.f;
        if ((unsigned)gh < 32u && (unsigned)wi < 32u)
            v = x[(((size_t)b * 64 + ic) * 64 + s) * 1024 + gh * 32 + wi];
        __nv_bfloat16 hb = __float2bfloat16(v);
        __nv_bfloat16 lb = __float2bfloat16(v - __bfloat162float(hb));
        int o = (h * 34 + w) * 72 + ic;
        Xhi[o] = us_of(hb);
        Xlo[o] = us_of(lb);
    }
    __syncthreads();

    float acc[4][3][4];
#pragma unroll
    for (int mg = 0; mg < 4; mg++)
#pragma unroll
        for (int j = 0; j < 3; j++)
#pragma unroll
            for (int r = 0; r < 4; r++) acc[mg][j][r] = 0.f;

    const int kb_lane = ((lane >> 4) & 1) * 16;   // +8 k for mats 2,3

    for (int tap = 0; tap < 9; tap++) {
        const int dh = tap / 3, dw = tap - dh * 3;
        u32 rowoff[4];
#pragma unroll
        for (int mg = 0; mg < 4; mg++) {
            int p = warpM * 64 + mg * 16 + ((lane >> 3) & 1) * 8 + (lane & 7);
            int row = ((p >> 5) + dh) * 34 + (p & 31) + dw;
            rowoff[mg] = (u32)row * 144;
        }
        const uint4* bbase = g_Bfq + ((tap * 4) * 12 + warpN * 3) * 32 + lane;
#pragma unroll
        for (int ks = 0; ks < 4; ks++) {
            uint4 B0 = bbase[ks * 12 * 32];
            uint4 B1 = bbase[ks * 12 * 32 + 32];
            uint4 B2 = bbase[ks * 12 * 32 + 64];
            const u32 kbyte = (u32)ks * 32 + kb_lane;
#pragma unroll
            for (int mg = 0; mg < 4; mg++) {
                u32 ahi[4], alo[4];
                ldsm4(ahi, sb + rowoff[mg] + kbyte);
                ldsm4(alo, sb + 29376 + rowoff[mg] + kbyte);
                mma_bf16(acc[mg][0], ahi, B0.x, B0.y);
                mma_bf16(acc[mg][0], alo, B0.x, B0.y);
                mma_bf16(acc[mg][0], ahi, B0.z, B0.w);
                mma_bf16(acc[mg][1], ahi, B1.x, B1.y);
                mma_bf16(acc[mg][1], alo, B1.x, B1.y);
                mma_bf16(acc[mg][1], ahi, B1.z, B1.w);
                mma_bf16(acc[mg][2], ahi, B2.x, B2.y);
                mma_bf16(acc[mg][2], alo, B2.x, B2.y);
                mma_bf16(acc[mg][2], ahi, B2.z, B2.w);
            }
        }
    }

    // ---- epilogue: stage [n][m] in smem, then coalesced out + bias ----
    __syncthreads();
    float* stage = (float*)sm;                       // [96][132]
#pragma unroll
    for (int mg = 0; mg < 4; mg++)
#pragma unroll
        for (int j = 0; j < 3; j++)
#pragma unroll
            for (int r = 0; r < 4; r++) {
                int n = warpN * 24 + j * 8 + (lane & 3) * 2 + (r & 1);
                int m = warpM * 64 + mg * 16 + (lane >> 2) + ((r >> 1) & 1) * 8;
                stage[n * 132 + m] = acc[mg][j][r];
            }
    __syncthreads();
    for (int i = tid; i < 96 * 128; i += 256) {
        int n = i >> 7, m = i & 127;
        float v = stage[n * 132 + m];
        float* dst; float bias; int ch;
        if (n < 32)      { dst = g_q; ch = n;      bias = __ldg(bq + ch); }
        else if (n < 64) { dst = g_k; ch = n - 32; bias = __ldg(bk + ch); }
        else             { dst = g_v; ch = n - 64; bias = __ldg(bv + ch); }
        dst[(((size_t)b * 32 + ch) * 64 + s) * 1024 + strip * 128 + m] = v + bias;
    }
}

// ---------------------------------------------------------------------------
// oconv via mma.sync bf16 3-pass.  M=128 x N=64, Cin=32.
// Warp tile 64 x 16 (4 m16 x 2 n8). X stride 40 (80B rows, conflict-free).
// ---------------------------------------------------------------------------
#define OCONV_SMEM 33792

__global__ __launch_bounds__(256, 2) void oconv_mma(
    const float* __restrict__ bo, float* __restrict__ out)
{
    extern __shared__ __align__(16) unsigned char sm[];
    unsigned short* Xhi = (unsigned short*)sm;           // 8160 elems (16320 B)
    unsigned short* Xlo = Xhi + 8160;
    const int strip = blockIdx.x, s = blockIdx.y, b = blockIdx.z;
    const int tid = threadIdx.x;
    const int wid = tid >> 5, lane = tid & 31;
    const int warpM = wid >> 2, warpN = wid & 3;
    const u32 sb = smem_u32(sm);

    for (int i = tid; i < 6 * 34 * 32; i += 256) {
        int ic = i / 204; int rem = i - ic * 204;
        int h = rem / 34, w = rem - h * 34;
        int gh = strip * 4 + h - 1, wi = w - 1;
        float v = 0.f;
        if ((unsigned)gh < 32u && (unsigned)wi < 32u)
            v = g_ao[(((size_t)b * 32 + ic) * 64 + s) * 1024 + gh * 32 + wi];
        __nv_bfloat16 hb = __float2bfloat16(v);
        __nv_bfloat16 lb = __float2bfloat16(v - __bfloat162float(hb));
        int o = (h * 34 + w) * 40 + ic;
        Xhi[o] = us_of(hb);
        Xlo[o] = us_of(lb);
    }
    __syncthreads();

    float acc[4][2][4];
#pragma unroll
    for (int mg = 0; mg < 4; mg++)
#pragma unroll
        for (int j = 0; j < 2; j++)
#pragma unroll
            for (int r = 0; r < 4; r++) acc[mg][j][r] = 0.f;

    const int kb_lane = ((lane >> 4) & 1) * 16;

    for (int tap = 0; tap < 9; tap++) {
        const int dh = tap / 3, dw = tap - dh * 3;
        u32 rowoff[4];
#pragma unroll
        for (int mg = 0; mg < 4; mg++) {
            int p = warpM * 64 + mg * 16 + ((lane >> 3) & 1) * 8 + (lane & 7);
            int row = ((p >> 5) + dh) * 34 + (p & 31) + dw;
            rowoff[mg] = (u32)row * 80;
        }
        const uint4* bbase = g_Bfo + ((tap * 2) * 8 + warpN * 2) * 32 + lane;
#pragma unroll
        for (int ks = 0; ks < 2; ks++) {
            uint4 B0 = bbase[ks * 8 * 32];
            uint4 B1 = bbase[ks * 8 * 32 + 32];
            const u32 kbyte = (u32)ks * 32 + kb_lane;
#pragma unroll
            for (int mg = 0; mg < 4; mg++) {
                u32 ahi[4], alo[4];
                ldsm4(ahi, sb + rowoff[mg] + kbyte);
                ldsm4(alo, sb + 16320 + rowoff[mg] + kbyte);
                mma_bf16(acc[mg][0], ahi, B0.x, B0.y);
                mma_bf16(acc[mg][0], alo, B0.x, B0.y);
                mma_bf16(acc[mg][0], ahi, B0.z, B0.w);
                mma_bf16(acc[mg][1], ahi, B1.x, B1.y);
                mma_bf16(acc[mg][1], alo, B1.x, B1.y);
                mma_bf16(acc[mg][1], ahi, B1.z, B1.w);
            }
        }
    }

    __syncthreads();
    float* stage = (float*)sm;                       // [64][132]
#pragma unroll
    for (int mg = 0; mg < 4; mg++)
#pragma unroll
        for (int j = 0; j < 2; j++)
#pragma unroll
            for (int r = 0; r < 4; r++) {
                int n = warpN * 16 + j * 8 + (lane & 3) * 2 + (r & 1);
                int m = warpM * 64 + mg * 16 + (lane >> 2) + ((r >> 1) & 1) * 8;
                stage[n * 132 + m] = acc[mg][j][r];
            }
    __syncthreads();
    for (int i = tid; i < 64 * 128; i += 256) {
        int n = i >> 7, m = i & 127;
        float v = stage[n * 132 + m] + __ldg(bo + n);
        out[(((size_t)b * 64 + n) * 64 + s) * 1024 + strip * 128 + m] = v;
    }
}

// ---------------------------------------------------------------------------
// attention (scalar fp32, unchanged)
// ---------------------------------------------------------------------------
__global__ __launch_bounds__(256) void attn_kernel()
{
    __shared__ float A[64 * 64];
    __shared__ float Buf[4224];
    const int bc = blockIdx.x;
    const float* q = g_q + (size_t)bc * 65536;
    const float* k = g_k + (size_t)bc * 65536;
    const float* v = g_v + (size_t)bc * 65536;
    float*       o = g_ao + (size_t)bc * 65536;
    const int tid = threadIdx.x, ty = tid >> 4, tx = tid & 15;
    float* Qs = Buf;
    float* Ks = Buf + 2112;
    float sc[4][4];
#pragma unroll
    for (int a = 0; a < 4; a++)
#pragma unroll
        for (int c = 0; c < 4; c++) sc[a][c] = 0.f;

    for (int f0 = 0; f0 < 1024; f0 += 32) {
#pragma unroll
        for (int i = 0; i < 8; i++) {
            int idx = tid + i * 256;
            int row = idx >> 5, col = idx & 31;
            Qs[row * 33 + col] = q[row * 1024 + f0 + col];
            Ks[row * 33 + col] = k[row * 1024 + f0 + col];
        }
        __syncthreads();
#pragma unroll
        for (int ff = 0; ff < 32; ff++) {
            float qv[4], kv[4];
#pragma unroll
            for (int u = 0; u < 4; u++) qv[u] = Qs[(ty + 16 * u) * 33 + ff];
#pragma unroll
            for (int u = 0; u < 4; u++) kv[u] = Ks[(tx + 16 * u) * 33 + ff];
#pragma unroll
            for (int us = 0; us < 4; us++)
#pragma unroll
                for (int ut = 0; ut < 4; ut++)
                    sc[us][ut] = fmaf(qv[us], kv[ut], sc[us][ut]);
        }
        __syncthreads();
    }
#pragma unroll
    for (int us = 0; us < 4; us++)
#pragma unroll
        for (int ut = 0; ut < 4; ut++) {
            float z = sc[us][ut] * 0.03125f;
            A[(ty + 16 * us) * 64 + (tx + 16 * ut)] = 1.f / (1.f + __expf(-z));
        }
    __syncthreads();

    float* Vs = Buf;
    for (int f0 = 0; f0 < 1024; f0 += 64) {
#pragma unroll
        for (int i = 0; i < 16; i++) {
            int idx = tid + i * 256;
            int row = idx >> 6, col = idx & 63;
            Vs[row * 65 + col] = v[row * 1024 + f0 + col];
        }
        __syncthreads();
        float oacc[4][4];
#pragma unroll
        for (int a = 0; a < 4; a++)
#pragma unroll
            for (int c = 0; c < 4; c++) oacc[a][c] = 0.f;
        for (int t = 0; t < 64; t++) {
            float av[4], vv[4];
#pragma unroll
            for (int u = 0; u < 4; u++) av[u] = A[(ty + 16 * u) * 64 + t];
#pragma unroll
            for (int u = 0; u < 4; u++) vv[u] = Vs[t * 65 + tx + 16 * u];
#pragma unroll
            for (int us = 0; us < 4; us++)
#pragma unroll
                for (int uf = 0; uf < 4; uf++)
                    oacc[us][uf] = fmaf(av[us], vv[uf], oacc[us][uf]);
        }
#pragma unroll
        for (int us = 0; us < 4; us++)
#pragma unroll
            for (int uf = 0; uf < 4; uf++)
                o[(ty + 16 * us) * 1024 + f0 + tx + 16 * uf] = oacc[us][uf];
        __syncthreads();
    }
}

// ---------------------------------------------------------------------------
// kernel_launch
// ---------------------------------------------------------------------------
extern "C" void kernel_launch(void* const* d_in, const int* in_sizes, int n_in,
                              void* d_out, int out_size) {
    const float* x  = (const float*)d_in[0];
    const float* wq = (const float*)d_in[1];
    const float* bq = (const float*)d_in[2];
    const float* wk = (const float*)d_in[3];
    const float* bk = (const float*)d_in[4];
    const float* wv = (const float*)d_in[5];
    const float* bv = (const float*)d_in[6];
    const float* wo = (const float*)d_in[7];
    const float* bo = (const float*)d_in[8];
    float* out = (float*)d_out;

    static int configured = 0;
    if (!configured) {
        cudaFuncSetAttribute(qkv_mma, cudaFuncAttributeMaxDynamicSharedMemorySize, QKV_SMEM);
        cudaFuncSetAttribute(oconv_mma, cudaFuncAttributeMaxDynamicSharedMemorySize, OCONV_SMEM);
        configured = 1;
    }

    pack_qkv_frag<<<(9 * 4 * 12 * 32 + 255) / 256, 256>>>(wq, wk, wv);
    pack_o_frag<<<(9 * 2 * 8 * 32 + 255) / 256, 256>>>(wo);

    dim3 cgrid(8, 64, 16);
    qkv_mma<<<cgrid, 256, QKV_SMEM>>>(x, bq, bk, bv);
    attn_kernel<<<512, 256>>>();
    oconv_mma<<<cgrid, 256, OCONV_SMEM>>>(bo, out);
}

// round 9
// speedup vs baseline: 3.0712x; 1.0387x over previous
#include <cuda_runtime.h>
#include <cuda_bf16.h>

typedef unsigned long long ull;
typedef unsigned int u32;

// ---------------------------------------------------------------------------
// Scratch: q/k/v and attn-out stored as bf16 hi/lo planes [b][c][s][hw]
// ---------------------------------------------------------------------------
#define PLANE_ELEMS 33554432
static __device__ unsigned short g_qh[PLANE_ELEMS], g_ql[PLANE_ELEMS];
static __device__ unsigned short g_kh[PLANE_ELEMS], g_kl[PLANE_ELEMS];
static __device__ unsigned short g_vh[PLANE_ELEMS], g_vl[PLANE_ELEMS];
static __device__ unsigned short g_aoh[PLANE_ELEMS], g_aol[PLANE_ELEMS];

// B fragments, prepacked in mma.sync fragment order.
static __device__ __align__(16) uint4 g_Bfq[9 * 4 * 12 * 32];
static __device__ __align__(16) uint4 g_Bfo[9 * 2 * 8 * 32];

// ---------------------------------------------------------------------------
// helpers
// ---------------------------------------------------------------------------
__device__ __forceinline__ u32 smem_u32(const void* p) {
    u32 a;
    asm("{ .reg .u64 t; cvta.to.shared.u64 t, %1; cvt.u32.u64 %0, t; }" : "=r"(a) : "l"(p));
    return a;
}
__device__ __forceinline__ unsigned short us_of(__nv_bfloat16 h) {
    return *reinterpret_cast<unsigned short*>(&h);
}
__device__ __forceinline__ void split_bf(float v, unsigned short& h, unsigned short& l) {
    __nv_bfloat16 hb = __float2bfloat16(v);
    h = us_of(hb);
    l = us_of(__float2bfloat16(v - __bfloat162float(hb)));
}
__device__ __forceinline__ void ldsm4(u32* r, u32 addr) {
    asm volatile("ldmatrix.sync.aligned.m8n8.x4.shared.b16 {%0,%1,%2,%3}, [%4];"
                 : "=r"(r[0]), "=r"(r[1]), "=r"(r[2]), "=r"(r[3]) : "r"(addr));
}
__device__ __forceinline__ void ldsm4t(u32* r, u32 addr) {
    asm volatile("ldmatrix.sync.aligned.m8n8.x4.trans.shared.b16 {%0,%1,%2,%3}, [%4];"
                 : "=r"(r[0]), "=r"(r[1]), "=r"(r[2]), "=r"(r[3]) : "r"(addr));
}
__device__ __forceinline__ void mma_bf16(float* c, const u32* a, u32 b0, u32 b1) {
    asm volatile(
        "mma.sync.aligned.m16n8k16.row.col.f32.bf16.bf16.f32 "
        "{%0,%1,%2,%3}, {%4,%5,%6,%7}, {%8,%9}, {%0,%1,%2,%3};"
        : "+f"(c[0]), "+f"(c[1]), "+f"(c[2]), "+f"(c[3])
        : "r"(a[0]), "r"(a[1]), "r"(a[2]), "r"(a[3]), "r"(b0), "r"(b1));
}
__device__ __forceinline__ void cpa16(u32 dst, const void* src) {
    asm volatile("cp.async.cg.shared.global [%0], [%1], 16;" :: "r"(dst), "l"(src));
}
#define CPA_COMMIT() asm volatile("cp.async.commit_group;" ::: "memory")
#define CPA_WAIT1()  asm volatile("cp.async.wait_group 1;" ::: "memory")
#define CPA_WAIT0()  asm volatile("cp.async.wait_group 0;" ::: "memory")

// ---------------------------------------------------------------------------
// Weight fragment pre-pack (unchanged)
// ---------------------------------------------------------------------------
__global__ void pack_qkv_frag(const float* __restrict__ wq, const float* __restrict__ wk,
                              const float* __restrict__ wv)
{
    int idx = blockIdx.x * 256 + threadIdx.x;
    if (idx >= 9 * 4 * 12 * 32) return;
    int lane = idx & 31; int t = idx >> 5;
    int n8 = t % 12; t /= 12;
    int ks = t & 3;  int tap = t >> 2;
    int dh = tap / 3, dw = tap % 3;
    int n = n8 * 8 + (lane >> 2);
    const float* src = (n < 32) ? wq + n * 576
                     : (n < 64) ? wk + (n - 32) * 576
                                : wv + (n - 64) * 576;
    u32 u[4];
#pragma unroll
    for (int r = 0; r < 2; r++) {
        int ic0 = ks * 16 + r * 8 + (lane & 3) * 2;
        float w0 = src[ic0 * 9 + dh * 3 + dw];
        float w1 = src[(ic0 + 1) * 9 + dh * 3 + dw];
        unsigned short h0, l0, h1, l1;
        split_bf(w0, h0, l0); split_bf(w1, h1, l1);
        u[r]     = (u32)h0 | ((u32)h1 << 16);
        u[2 + r] = (u32)l0 | ((u32)l1 << 16);
    }
    g_Bfq[idx] = make_uint4(u[0], u[1], u[2], u[3]);
}

__global__ void pack_o_frag(const float* __restrict__ wo)
{
    int idx = blockIdx.x * 256 + threadIdx.x;
    if (idx >= 9 * 2 * 8 * 32) return;
    int lane = idx & 31; int t = idx >> 5;
    int n8 = t & 7; t >>= 3;
    int ks = t & 1;  int tap = t >> 1;
    int dh = tap / 3, dw = tap % 3;
    int n = n8 * 8 + (lane >> 2);
    const float* src = wo + n * 288;
    u32 u[4];
#pragma unroll
    for (int r = 0; r < 2; r++) {
        int ic0 = ks * 16 + r * 8 + (lane & 3) * 2;
        float w0 = src[ic0 * 9 + dh * 3 + dw];
        float w1 = src[(ic0 + 1) * 9 + dh * 3 + dw];
        unsigned short h0, l0, h1, l1;
        split_bf(w0, h0, l0); split_bf(w1, h1, l1);
        u[r]     = (u32)h0 | ((u32)h1 << 16);
        u[2 + r] = (u32)l0 | ((u32)l1 << 16);
    }
    g_Bfo[idx] = make_uint4(u[0], u[1], u[2], u[3]);
}

// ---------------------------------------------------------------------------
// qkv conv via mma.sync bf16 3-pass.  Epilogue writes bf16 hi/lo planes.
// ---------------------------------------------------------------------------
#define QKV_SMEM 58752

__global__ __launch_bounds__(256, 2) void qkv_mma(
    const float* __restrict__ x,
    const float* __restrict__ bq, const float* __restrict__ bk,
    const float* __restrict__ bv)
{
    extern __shared__ __align__(16) unsigned char sm[];
    unsigned short* Xhi = (unsigned short*)sm;           // 14688 elems
    unsigned short* Xlo = Xhi + 14688;
    const int strip = blockIdx.x, s = blockIdx.y, b = blockIdx.z;
    const int tid = threadIdx.x;
    const int wid = tid >> 5, lane = tid & 31;
    const int warpM = wid >> 2, warpN = wid & 3;
    const u32 sb = smem_u32(sm);

    for (int i = tid; i < 6 * 34 * 64; i += 256) {
        int ic = i / 204; int rem = i - ic * 204;
        int h = rem / 34, w = rem - h * 34;
        int gh = strip * 4 + h - 1, wi = w - 1;
        float v = 0.f;
        if ((unsigned)gh < 32u && (unsigned)wi < 32u)
            v = x[(((size_t)b * 64 + ic) * 64 + s) * 1024 + gh * 32 + wi];
        unsigned short hb, lb; split_bf(v, hb, lb);
        int o = (h * 34 + w) * 72 + ic;
        Xhi[o] = hb; Xlo[o] = lb;
    }
    __syncthreads();

    float acc[4][3][4];
#pragma unroll
    for (int mg = 0; mg < 4; mg++)
#pragma unroll
        for (int j = 0; j < 3; j++)
#pragma unroll
            for (int r = 0; r < 4; r++) acc[mg][j][r] = 0.f;

    const int kb_lane = ((lane >> 4) & 1) * 16;

    for (int tap = 0; tap < 9; tap++) {
        const int dh = tap / 3, dw = tap - dh * 3;
        u32 rowoff[4];
#pragma unroll
        for (int mg = 0; mg < 4; mg++) {
            int p = warpM * 64 + mg * 16 + ((lane >> 3) & 1) * 8 + (lane & 7);
            int row = ((p >> 5) + dh) * 34 + (p & 31) + dw;
            rowoff[mg] = (u32)row * 144;
        }
        const uint4* bbase = g_Bfq + ((tap * 4) * 12 + warpN * 3) * 32 + lane;
#pragma unroll
        for (int ks = 0; ks < 4; ks++) {
            uint4 B0 = bbase[ks * 12 * 32];
            uint4 B1 = bbase[ks * 12 * 32 + 32];
            uint4 B2 = bbase[ks * 12 * 32 + 64];
            const u32 kbyte = (u32)ks * 32 + kb_lane;
#pragma unroll
            for (int mg = 0; mg < 4; mg++) {
                u32 ahi[4], alo[4];
                ldsm4(ahi, sb + rowoff[mg] + kbyte);
                ldsm4(alo, sb + 29376 + rowoff[mg] + kbyte);
                mma_bf16(acc[mg][0], ahi, B0.x, B0.y);
                mma_bf16(acc[mg][0], alo, B0.x, B0.y);
                mma_bf16(acc[mg][0], ahi, B0.z, B0.w);
                mma_bf16(acc[mg][1], ahi, B1.x, B1.y);
                mma_bf16(acc[mg][1], alo, B1.x, B1.y);
                mma_bf16(acc[mg][1], ahi, B1.z, B1.w);
                mma_bf16(acc[mg][2], ahi, B2.x, B2.y);
                mma_bf16(acc[mg][2], alo, B2.x, B2.y);
                mma_bf16(acc[mg][2], ahi, B2.z, B2.w);
            }
        }
    }

    __syncthreads();
    float* stage = (float*)sm;                       // [96][132]
#pragma unroll
    for (int mg = 0; mg < 4; mg++)
#pragma unroll
        for (int j = 0; j < 3; j++)
#pragma unroll
            for (int r = 0; r < 4; r++) {
                int n = warpN * 24 + j * 8 + (lane & 3) * 2 + (r & 1);
                int m = warpM * 64 + mg * 16 + (lane >> 2) + ((r >> 1) & 1) * 8;
                stage[n * 132 + m] = acc[mg][j][r];
            }
    __syncthreads();
    for (int i = tid; i < 96 * 64; i += 256) {
        int n = i >> 6, mp = (i & 63) * 2;
        unsigned short *dh, *dl; float bias; int ch;
        if (n < 32)      { dh = g_qh; dl = g_ql; ch = n;      bias = __ldg(bq + ch); }
        else if (n < 64) { dh = g_kh; dl = g_kl; ch = n - 32; bias = __ldg(bk + ch); }
        else             { dh = g_vh; dl = g_vl; ch = n - 64; bias = __ldg(bv + ch); }
        float v0 = stage[n * 132 + mp] + bias;
        float v1 = stage[n * 132 + mp + 1] + bias;
        unsigned short h0, l0, h1, l1;
        split_bf(v0, h0, l0); split_bf(v1, h1, l1);
        size_t o = (((size_t)b * 32 + ch) * 64 + s) * 1024 + strip * 128 + mp;
        *(u32*)(dh + o) = (u32)h0 | ((u32)h1 << 16);
        *(u32*)(dl + o) = (u32)l0 | ((u32)l1 << 16);
    }
}

// ---------------------------------------------------------------------------
// Tensorized attention.  Grid 512 (one (b,c)), block 256 (8 warps).
// Phase A: A = sigmoid(Q K^T / 32)  (M=64,N=64,K=1024, bf16 3-pass, cp.async)
// Phase B: O = A V                  (K=64, 16 f-chunks of 64)
// smem: A planes hi/lo [64][72]; staging 2 stages x 4 planes [64][72]
// ---------------------------------------------------------------------------
#define ATT_AH   0
#define ATT_AL   9216
#define ATT_BUF  18432
#define ATT_STG  36864
#define ATT_SMEM 92160

__global__ __launch_bounds__(256, 2) void attn_mma()
{
    extern __shared__ __align__(16) unsigned char sm[];
    const int bc = blockIdx.x;
    const int tid = threadIdx.x;
    const int wid = tid >> 5, lane = tid & 31;
    const int warpM = wid >> 2, warpN = wid & 3;   // 2 x 4
    const u32 sb = smem_u32(sm);
    const size_t gb = (size_t)bc * 65536;

    // lane address components
    u32 a_rowoff[2];
#pragma unroll
    for (int mg = 0; mg < 2; mg++) {
        int p = warpM * 32 + mg * 16 + ((lane >> 3) & 1) * 8 + (lane & 7);
        a_rowoff[mg] = (u32)p * 144;
    }
    const u32 a_kb = ((lane >> 4) & 1) * 16;
    const int n0 = warpN * 16;
    const u32 b_rowoff = (u32)(n0 + (lane & 7) + ((lane >> 4) & 1) * 8) * 144;
    const u32 b_kb = ((lane >> 3) & 1) * 16;
    // V (trans) components
    const int v_row = (lane & 7) + ((lane >> 3) & 1) * 8;
    const u32 v_fb = ((lane >> 4) & 1) * 16 + warpN * 32;

    // ---- phase A ----
    auto issueA = [&](int f0, int stg) {
#pragma unroll
        for (int j = 0; j < 8; j++) {
            int idx = tid + j * 256;             // < 2048
            int plane = idx >> 9;
            int r = (idx >> 3) & 63;
            int col = idx & 7;
            const unsigned short* src =
                (plane == 0) ? g_qh : (plane == 1) ? g_ql :
                (plane == 2) ? g_kh : g_kl;
            cpa16(sb + ATT_BUF + stg * ATT_STG + plane * 9216 + r * 144 + col * 16,
                  src + gb + (size_t)r * 1024 + f0 + col * 8);
        }
        CPA_COMMIT();
    };

    float acc[2][2][4];
#pragma unroll
    for (int mg = 0; mg < 2; mg++)
#pragma unroll
        for (int nt = 0; nt < 2; nt++)
#pragma unroll
            for (int r = 0; r < 4; r++) acc[mg][nt][r] = 0.f;

    issueA(0, 0);
    for (int c = 0; c < 16; c++) {
        const int stg = c & 1;
        if (c + 1 < 16) { issueA((c + 1) * 64, (c + 1) & 1); CPA_WAIT1(); }
        else            { CPA_WAIT0(); }
        __syncthreads();
        const u32 base = sb + ATT_BUF + stg * ATT_STG;
#pragma unroll
        for (int ks = 0; ks < 4; ks++) {
            u32 bh[4], bl[4];
            ldsm4(bh, base + 18432 + b_rowoff + ks * 32 + b_kb);
            ldsm4(bl, base + 27648 + b_rowoff + ks * 32 + b_kb);
#pragma unroll
            for (int mg = 0; mg < 2; mg++) {
                u32 ah[4], al[4];
                ldsm4(ah, base + a_rowoff[mg] + ks * 32 + a_kb);
                ldsm4(al, base + 9216 + a_rowoff[mg] + ks * 32 + a_kb);
                mma_bf16(acc[mg][0], ah, bh[0], bh[1]);
                mma_bf16(acc[mg][0], al, bh[0], bh[1]);
                mma_bf16(acc[mg][0], ah, bl[0], bl[1]);
                mma_bf16(acc[mg][1], ah, bh[2], bh[3]);
                mma_bf16(acc[mg][1], al, bh[2], bh[3]);
                mma_bf16(acc[mg][1], ah, bl[2], bl[3]);
            }
        }
        __syncthreads();
    }

    // ---- sigmoid -> A planes (hi/lo) ----
    unsigned short* Ah = (unsigned short*)(sm + ATT_AH);
    unsigned short* Al = (unsigned short*)(sm + ATT_AL);
#pragma unroll
    for (int mg = 0; mg < 2; mg++)
#pragma unroll
        for (int nt = 0; nt < 2; nt++)
#pragma unroll
            for (int half = 0; half < 2; half++) {
                int row = warpM * 32 + mg * 16 + (lane >> 2) + half * 8;
                int n = n0 + nt * 8 + (lane & 3) * 2;
                float z0 = acc[mg][nt][half * 2 + 0] * 0.03125f;
                float z1 = acc[mg][nt][half * 2 + 1] * 0.03125f;
                float a0 = 1.f / (1.f + __expf(-z0));
                float a1 = 1.f / (1.f + __expf(-z1));
                unsigned short h0, l0, h1, l1;
                split_bf(a0, h0, l0); split_bf(a1, h1, l1);
                *(u32*)(Ah + row * 72 + n) = (u32)h0 | ((u32)h1 << 16);
                *(u32*)(Al + row * 72 + n) = (u32)l0 | ((u32)l1 << 16);
            }

    // ---- phase B ----
    auto issueB = [&](int f0, int stg) {
#pragma unroll
        for (int j = 0; j < 4; j++) {
            int idx = tid + j * 256;             // < 1024
            int plane = idx >> 9;
            int r = (idx >> 3) & 63;
            int col = idx & 7;
            const unsigned short* src = (plane == 0) ? g_vh : g_vl;
            cpa16(sb + ATT_BUF + stg * 18432 + plane * 9216 + r * 144 + col * 16,
                  src + gb + (size_t)r * 1024 + f0 + col * 8);
        }
        CPA_COMMIT();
    };

    issueB(0, 0);
    __syncthreads();   // A planes visible to all + V0 in flight

    for (int c = 0; c < 16; c++) {
        const int stg = c & 1;
        if (c + 1 < 16) { issueB((c + 1) * 64, (c + 1) & 1); CPA_WAIT1(); }
        else            { CPA_WAIT0(); }
        __syncthreads();
        const u32 base = sb + ATT_BUF + stg * 18432;
        float oa[2][2][4];
#pragma unroll
        for (int mg = 0; mg < 2; mg++)
#pragma unroll
            for (int nt = 0; nt < 2; nt++)
#pragma unroll
                for (int r = 0; r < 4; r++) oa[mg][nt][r] = 0.f;
#pragma unroll
        for (int ks = 0; ks < 4; ks++) {
            u32 vh[4], vl[4];
            ldsm4t(vh, base + (u32)(ks * 16 + v_row) * 144 + v_fb);
            ldsm4t(vl, base + 9216 + (u32)(ks * 16 + v_row) * 144 + v_fb);
#pragma unroll
            for (int mg = 0; mg < 2; mg++) {
                u32 ah[4], al[4];
                ldsm4(ah, sb + ATT_AH + a_rowoff[mg] + ks * 32 + a_kb);
                ldsm4(al, sb + ATT_AL + a_rowoff[mg] + ks * 32 + a_kb);
                mma_bf16(oa[mg][0], ah, vh[0], vh[1]);
                mma_bf16(oa[mg][0], al, vh[0], vh[1]);
                mma_bf16(oa[mg][0], ah, vl[0], vl[1]);
                mma_bf16(oa[mg][1], ah, vh[2], vh[3]);
                mma_bf16(oa[mg][1], al, vh[2], vh[3]);
                mma_bf16(oa[mg][1], ah, vl[2], vl[3]);
            }
        }
        // write O chunk as hi/lo planes
        const int f0 = c * 64;
#pragma unroll
        for (int mg = 0; mg < 2; mg++)
#pragma unroll
            for (int nt = 0; nt < 2; nt++)
#pragma unroll
                for (int half = 0; half < 2; half++) {
                    int row = warpM * 32 + mg * 16 + (lane >> 2) + half * 8;
                    int f = f0 + warpN * 16 + nt * 8 + (lane & 3) * 2;
                    float v0 = oa[mg][nt][half * 2 + 0];
                    float v1 = oa[mg][nt][half * 2 + 1];
                    unsigned short h0, l0, h1, l1;
                    split_bf(v0, h0, l0); split_bf(v1, h1, l1);
                    size_t o = gb + (size_t)row * 1024 + f;
                    *(u32*)(g_aoh + o) = (u32)h0 | ((u32)h1 << 16);
                    *(u32*)(g_aol + o) = (u32)l0 | ((u32)l1 << 16);
                }
        __syncthreads();
    }
}

// ---------------------------------------------------------------------------
// oconv via mma.sync bf16 3-pass. Halo now copies bf16 planes (no cvt).
// ---------------------------------------------------------------------------
#define OCONV_SMEM 33792

__global__ __launch_bounds__(256, 2) void oconv_mma(
    const float* __restrict__ bo, float* __restrict__ out)
{
    extern __shared__ __align__(16) unsigned char sm[];
    unsigned short* Xhi = (unsigned short*)sm;           // 8160 elems
    unsigned short* Xlo = Xhi + 8160;
    const int strip = blockIdx.x, s = blockIdx.y, b = blockIdx.z;
    const int tid = threadIdx.x;
    const int wid = tid >> 5, lane = tid & 31;
    const int warpM = wid >> 2, warpN = wid & 3;
    const u32 sb = smem_u32(sm);

    for (int i = tid; i < 6 * 34 * 32; i += 256) {
        int ic = i / 204; int rem = i - ic * 204;
        int h = rem / 34, w = rem - h * 34;
        int gh = strip * 4 + h - 1, wi = w - 1;
        unsigned short vh = 0, vl = 0;
        if ((unsigned)gh < 32u && (unsigned)wi < 32u) {
            size_t o = (((size_t)b * 32 + ic) * 64 + s) * 1024 + gh * 32 + wi;
            vh = g_aoh[o]; vl = g_aol[o];
        }
        int o2 = (h * 34 + w) * 40 + ic;
        Xhi[o2] = vh; Xlo[o2] = vl;
    }
    __syncthreads();

    float acc[4][2][4];
#pragma unroll
    for (int mg = 0; mg < 4; mg++)
#pragma unroll
        for (int j = 0; j < 2; j++)
#pragma unroll
            for (int r = 0; r < 4; r++) acc[mg][j][r] = 0.f;

    const int kb_lane = ((lane >> 4) & 1) * 16;

    for (int tap = 0; tap < 9; tap++) {
        const int dh = tap / 3, dw = tap - dh * 3;
        u32 rowoff[4];
#pragma unroll
        for (int mg = 0; mg < 4; mg++) {
            int p = warpM * 64 + mg * 16 + ((lane >> 3) & 1) * 8 + (lane & 7);
            int row = ((p >> 5) + dh) * 34 + (p & 31) + dw;
            rowoff[mg] = (u32)row * 80;
        }
        const uint4* bbase = g_Bfo + ((tap * 2) * 8 + warpN * 2) * 32 + lane;
#pragma unroll
        for (int ks = 0; ks < 2; ks++) {
            uint4 B0 = bbase[ks * 8 * 32];
            uint4 B1 = bbase[ks * 8 * 32 + 32];
            const u32 kbyte = (u32)ks * 32 + kb_lane;
#pragma unroll
            for (int mg = 0; mg < 4; mg++) {
                u32 ahi[4], alo[4];
                ldsm4(ahi, sb + rowoff[mg] + kbyte);
                ldsm4(alo, sb + 16320 + rowoff[mg] + kbyte);
                mma_bf16(acc[mg][0], ahi, B0.x, B0.y);
                mma_bf16(acc[mg][0], alo, B0.x, B0.y);
                mma_bf16(acc[mg][0], ahi, B0.z, B0.w);
                mma_bf16(acc[mg][1], ahi, B1.x, B1.y);
                mma_bf16(acc[mg][1], alo, B1.x, B1.y);
                mma_bf16(acc[mg][1], ahi, B1.z, B1.w);
            }
        }
    }

    __syncthreads();
    float* stage = (float*)sm;                       // [64][132]
#pragma unroll
    for (int mg = 0; mg < 4; mg++)
#pragma unroll
        for (int j = 0; j < 2; j++)
#pragma unroll
            for (int r = 0; r < 4; r++) {
                int n = warpN * 16 + j * 8 + (lane & 3) * 2 + (r & 1);
                int m = warpM * 64 + mg * 16 + (lane >> 2) + ((r >> 1) & 1) * 8;
                stage[n * 132 + m] = acc[mg][j][r];
            }
    __syncthreads();
    for (int i = tid; i < 64 * 128; i += 256) {
        int n = i >> 7, m = i & 127;
        float v = stage[n * 132 + m] + __ldg(bo + n);
        out[(((size_t)b * 64 + n) * 64 + s) * 1024 + strip * 128 + m] = v;
    }
}

// ---------------------------------------------------------------------------
// kernel_launch
// ---------------------------------------------------------------------------
extern "C" void kernel_launch(void* const* d_in, const int* in_sizes, int n_in,
                              void* d_out, int out_size) {
    const float* x  = (const float*)d_in[0];
    const float* wq = (const float*)d_in[1];
    const float* bq = (const float*)d_in[2];
    const float* wk = (const float*)d_in[3];
    const float* bk = (const float*)d_in[4];
    const float* wv = (const float*)d_in[5];
    const float* bv = (const float*)d_in[6];
    const float* wo = (const float*)d_in[7];
    const float* bo = (const float*)d_in[8];
    float* out = (float*)d_out;

    static int configured = 0;
    if (!configured) {
        cudaFuncSetAttribute(qkv_mma, cudaFuncAttributeMaxDynamicSharedMemorySize, QKV_SMEM);
        cudaFuncSetAttribute(attn_mma, cudaFuncAttributeMaxDynamicSharedMemorySize, ATT_SMEM);
        cudaFuncSetAttribute(oconv_mma, cudaFuncAttributeMaxDynamicSharedMemorySize, OCONV_SMEM);
        configured = 1;
    }

    pack_qkv_frag<<<(9 * 4 * 12 * 32 + 255) / 256, 256>>>(wq, wk, wv);
    pack_o_frag<<<(9 * 2 * 8 * 32 + 255) / 256, 256>>>(wo);

    dim3 cgrid(8, 64, 16);
    qkv_mma<<<cgrid, 256, QKV_SMEM>>>(x, bq, bk, bv);
    attn_mma<<<512, 256, ATT_SMEM>>>();
    oconv_mma<<<cgrid, 256, OCONV_SMEM>>>(bo, out);
}